// round 7
// baseline (speedup 1.0000x reference)
#include <cuda_runtime.h>

// ---------------- problem constants ----------------
#define PN    8192
#define WD    256
#define HD    256
#define TANXc 0.5f
#define TANYc 0.5f
#define FXc   256.0f
#define FYc   256.0f
#define TSZ   8           // tile size in px
#define NTX   32          // tiles per row
#define NTILE 1024
#define TCAP  1024        // per-tile list capacity

typedef unsigned long long u64;

// ---------------- scratch ----------------
__device__ float4 g_d1[PN];              // x, y, A, B
__device__ float4 g_d2[PN];              // C, o, r, g
__device__ float  g_d3[PN];              // b
__device__ u64    g_tkey[NTILE * TCAP];  // per-tile unsorted keys
__device__ int    g_tcnt[NTILE];         // atomic counters (reset by raster each pass)

// ---------------- preprocess + per-tile binning (latency-optimized) ----------------
__global__ __launch_bounds__(64) void preprocess_kernel(
    const float* __restrict__ means, const float* __restrict__ cols,
    const float* __restrict__ ops, const float* __restrict__ scales,
    const float* __restrict__ rots, const float* __restrict__ Vm,
    const float* __restrict__ Pr)
{
    int i = blockIdx.x * blockDim.x + threadIdx.x;
    if (i >= PN) return;

    float mx = means[3*i+0], my = means[3*i+1], mz = means[3*i+2];

    float pv0 = mx*Vm[0] + my*Vm[4] + mz*Vm[8]  + Vm[12];
    float pv1 = mx*Vm[1] + my*Vm[5] + mz*Vm[9]  + Vm[13];
    float pv2 = mx*Vm[2] + my*Vm[6] + mz*Vm[10] + Vm[14];

    float ph0 = mx*Pr[0] + my*Pr[4] + mz*Pr[8]  + Pr[12];
    float ph1 = mx*Pr[1] + my*Pr[5] + mz*Pr[9]  + Pr[13];
    float ph3 = mx*Pr[3] + my*Pr[7] + mz*Pr[11] + Pr[15];
    float invw = __fdividef(1.0f, ph3 + 1e-7f);
    float m2x = ((ph0*invw + 1.0f) * (float)WD - 1.0f) * 0.5f;
    float m2y = ((ph1*invw + 1.0f) * (float)HD - 1.0f) * 0.5f;

    // quaternion -> rotation (rsqrt, no divides)
    float qr = rots[4*i+0], qx = rots[4*i+1], qy = rots[4*i+2], qz = rots[4*i+3];
    float qin = rsqrtf(qr*qr + qx*qx + qy*qy + qz*qz);
    qr *= qin; qx *= qin; qy *= qin; qz *= qin;
    float R[3][3];
    R[0][0] = 1.0f - 2.0f*(qy*qy + qz*qz); R[0][1] = 2.0f*(qx*qy - qr*qz); R[0][2] = 2.0f*(qx*qz + qr*qy);
    R[1][0] = 2.0f*(qx*qy + qr*qz); R[1][1] = 1.0f - 2.0f*(qx*qx + qz*qz); R[1][2] = 2.0f*(qy*qz - qr*qx);
    R[2][0] = 2.0f*(qx*qz - qr*qy); R[2][1] = 2.0f*(qy*qz + qr*qx); R[2][2] = 1.0f - 2.0f*(qx*qx + qy*qy);

    float s0 = scales[3*i+0], s1 = scales[3*i+1], s2 = scales[3*i+2];
    float sq0 = s0*s0, sq1 = s1*s1, sq2 = s2*s2;

    float Sg[3][3];
    #pragma unroll
    for (int r = 0; r < 3; r++)
        #pragma unroll
        for (int c = 0; c < 3; c++)
            Sg[r][c] = R[r][0]*sq0*R[c][0] + R[r][1]*sq1*R[c][1] + R[r][2]*sq2*R[c][2];

    float Mt[3][3], Cc[3][3];
    #pragma unroll
    for (int r = 0; r < 3; r++)
        #pragma unroll
        for (int k = 0; k < 3; k++)
            Mt[r][k] = Vm[0*4+r]*Sg[0][k] + Vm[1*4+r]*Sg[1][k] + Vm[2*4+r]*Sg[2][k];
    #pragma unroll
    for (int r = 0; r < 3; r++)
        #pragma unroll
        for (int l = 0; l < 3; l++)
            Cc[r][l] = Mt[r][0]*Vm[0*4+l] + Mt[r][1]*Vm[1*4+l] + Mt[r][2]*Vm[2*4+l];

    float tz  = pv2;
    float itz = __fdividef(1.0f, tz);
    float limx = 1.3f * TANXc, limy = 1.3f * TANYc;
    float txc = fminf(limx, fmaxf(-limx, pv0*itz)) * tz;
    float tyc = fminf(limy, fmaxf(-limy, pv1*itz)) * tz;
    float J00 = FXc*itz, J02 = -FXc*txc*itz*itz;
    float J11 = FYc*itz, J12 = -FYc*tyc*itz*itz;

    float T00 = J00*Cc[0][0] + J02*Cc[2][0];
    float T01 = J00*Cc[0][1] + J02*Cc[2][1];
    float T02 = J00*Cc[0][2] + J02*Cc[2][2];
    float T11 = J11*Cc[1][1] + J12*Cc[2][1];
    float T12 = J11*Cc[1][2] + J12*Cc[2][2];
    float c00 = T00*J00 + T02*J02;
    float c01 = T01*J11 + T02*J12;
    float c11 = T11*J11 + T12*J12;

    float a = c00 + 0.3f, b = c01, c = c11 + 0.3f;
    float det  = a*c - b*b;
    float idet = __fdividef(1.0f, det);
    float A  = c*idet, B = -b*idet, C2 = a*idet;

    float o   = ops[i];
    float tau = 2.0f * __logf(255.0f * o);
    float tq  = fmaxf(tau, 0.0f);
    float ex  = sqrtf(tq * a) + 1.0f;
    float ey  = sqrtf(tq * c) + 1.0f;

    g_d1[i] = make_float4(m2x, m2y, A, B);
    g_d2[i] = make_float4(C2, o, cols[3*i+0], cols[3*i+1]);
    g_d3[i] = cols[3*i+2];

    if (tau <= 0.0f) return;   // alpha can never reach 1/255

    // exact TSZ-px tile span of the AABB
    const float inv = 1.0f / (float)TSZ;
    int rx0 = max(0,       (int)ceilf ((m2x - ex - (float)(TSZ-1)) * inv));
    int rx1 = min(NTX - 1, (int)floorf((m2x + ex) * inv));
    int ry0 = max(0,       (int)ceilf ((m2y - ey - (float)(TSZ-1)) * inv));
    int ry1 = min(NTX - 1, (int)floorf((m2y + ey) * inv));
    if (rx0 > rx1 || ry0 > ry1) return;

    u64 key = ((u64)__float_as_uint(pv2) << 32) | (unsigned)i;
    int sw = rx1 - rx0, sh = ry1 - ry0;

    if (sw <= 3 && sh <= 3) {
        // fully unrolled, predicated: up to 16 INDEPENDENT atomics in flight
        #pragma unroll
        for (int dy = 0; dy < 4; dy++) {
            #pragma unroll
            for (int dx = 0; dx < 4; dx++) {
                if (dy <= sh && dx <= sw) {
                    int t = (ry0 + dy) * NTX + (rx0 + dx);
                    int pos = atomicAdd(&g_tcnt[t], 1);
                    if (pos < TCAP) g_tkey[t * TCAP + pos] = key;
                }
            }
        }
    } else {
        for (int ry = ry0; ry <= ry1; ry++)
            #pragma unroll 4
            for (int rx = rx0; rx <= rx1; rx++) {
                int t = ry * NTX + rx;
                int pos = atomicAdd(&g_tcnt[t], 1);
                if (pos < TCAP) g_tkey[t * TCAP + pos] = key;
            }
    }
}

// ---------------- fused per-tile sort + rasterize (1024 blocks, 64 threads) ----------------
__global__ __launch_bounds__(64) void raster_kernel(const float* __restrict__ bg,
                                                    float* __restrict__ out)
{
    const int tx = threadIdx.x, ty = threadIdx.y;
    const int tid = ty * TSZ + tx;
    const int pxi = blockIdx.x * TSZ + tx;
    const int pyi = blockIdx.y * TSZ + ty;
    const float pxf = (float)pxi, pyf = (float)pyi;

    const int r = (int)blockIdx.y * NTX + (int)blockIdx.x;
    const int n = min(g_tcnt[r], TCAP);
    if (tid == 0) g_tcnt[r] = 0;     // reset for next graph replay

    __shared__ u64    sk[TCAP];      // 8 KB keys
    __shared__ float4 s_a[64];       // x, y, A, B
    __shared__ float4 s_b[64];       // C, o, r, g
    __shared__ float  s_c[64];       // b

    // ---- in-block bitonic sort of this tile's keys (depth order) ----
    if (n > 0) {
        int m = 2;
        while (m < n) m <<= 1;
        for (int i = tid; i < m; i += 64)
            sk[i] = (i < n) ? g_tkey[r * TCAP + i] : ~0ull;
        __syncthreads();
        for (int k = 2; k <= m; k <<= 1) {
            for (int j = k >> 1; j > 0; j >>= 1) {
                for (int p = tid; p < (m >> 1); p += 64) {
                    int i  = ((p & ~(j - 1)) << 1) | (p & (j - 1));
                    bool up = ((i & k) == 0);
                    u64 x = sk[i], y = sk[i | j];
                    if ((x > y) == up) { sk[i] = y; sk[i | j] = x; }
                }
                __syncthreads();
            }
        }
    }

    // ---- ordered blend, staged 64 at a time via gathered loads ----
    float T = 1.0f;
    float ar = 0.0f, ag = 0.0f, ab = 0.0f;
    bool alive = true;

    for (int start = 0; start < n; start += 64) {
        int g = start + tid;
        if (g < n) {
            int s = (int)(sk[g] & 0xFFFFFFFFu);
            s_a[tid] = g_d1[s];
            s_b[tid] = g_d2[s];
            s_c[tid] = g_d3[s];
        }
        __syncthreads();
        int cnt = min(64, n - start);

        if (alive) {
            // software-pipelined: prefetch entry jj+1 while blending jj
            float4 na = s_a[0];
            float4 nb = s_b[0];
            float  nc = s_c[0];
            #pragma unroll 2
            for (int jj = 0; jj < cnt; jj++) {
                float4 ea = na;
                float4 eb = nb;
                float  ec = nc;
                int j1 = jj + 1;
                if (j1 < cnt) { na = s_a[j1]; nb = s_b[j1]; nc = s_c[j1]; }

                float dx = ea.x - pxf;
                float dy = ea.y - pyf;
                float power = -0.5f * (ea.z*dx*dx + eb.x*dy*dy) - ea.w*dx*dy;
                float raw = eb.y * __expf(power);     // unconditional; discarded if power>0
                if (power > 0.0f || raw < (1.0f / 255.0f)) continue;
                float alpha = fminf(0.99f, raw);
                float wgt = alpha * T;
                ar += wgt * eb.z;
                ag += wgt * eb.w;
                ab += wgt * ec;
                T *= (1.0f - alpha);
                if (T < 1e-6f) { alive = false; break; }
            }
        }
        int nalive = __syncthreads_count(alive ? 1 : 0);
        if (nalive == 0) break;
    }

    int pid = pyi * WD + pxi;
    out[pid]           = ar + T * bg[0];
    out[HD*WD + pid]   = ag + T * bg[1];
    out[2*HD*WD + pid] = ab + T * bg[2];
}

// ---------------- launch ----------------
extern "C" void kernel_launch(void* const* d_in, const int* in_sizes, int n_in,
                              void* d_out, int out_size)
{
    const float* means  = (const float*)d_in[0];
    const float* cols   = (const float*)d_in[1];
    const float* ops    = (const float*)d_in[2];
    const float* scales = (const float*)d_in[3];
    const float* rots   = (const float*)d_in[4];
    const float* bg     = (const float*)d_in[5];
    const float* Vm     = (const float*)d_in[6];
    const float* Pr     = (const float*)d_in[7];
    float* out = (float*)d_out;

    preprocess_kernel<<<PN/64, 64>>>(means, cols, ops, scales, rots, Vm, Pr);
    dim3 grid(WD/TSZ, HD/TSZ), block(TSZ, TSZ);
    raster_kernel<<<grid, block>>>(bg, out);
}

// round 8
// speedup vs baseline: 1.0529x; 1.0529x over previous
#include <cuda_runtime.h>

// ---------------- problem constants ----------------
#define PN    8192
#define WD    256
#define HD    256
#define TANXc 0.5f
#define TANYc 0.5f
#define FXc   256.0f
#define FYc   256.0f
#define TSZ   8           // tile size in px
#define NTX   32          // tiles per row
#define NTILE 1024
#define TCAP  1024        // per-tile list capacity

typedef unsigned long long u64;

// ---------------- scratch ----------------
__device__ float4 g_d1[PN];              // x, y, A, B
__device__ float4 g_d2[PN];              // C, o, r, g
__device__ float  g_d3[PN];              // b
__device__ u64    g_tkey[NTILE * TCAP];  // per-tile unsorted keys
__device__ int    g_tcnt[NTILE];         // atomic counters (reset by tile_sort)
__device__ int    g_scnt[NTILE];         // stable counts for raster
__device__ float4 g_ta[NTILE * TCAP];    // sorted: x, y, A, B
__device__ float4 g_tb[NTILE * TCAP];    // sorted: C, o, r, g
__device__ float  g_tc[NTILE * TCAP];    // sorted: b

// ---------------- preprocess + per-tile binning (latency-optimized) ----------------
__global__ __launch_bounds__(64) void preprocess_kernel(
    const float* __restrict__ means, const float* __restrict__ cols,
    const float* __restrict__ ops, const float* __restrict__ scales,
    const float* __restrict__ rots, const float* __restrict__ Vm,
    const float* __restrict__ Pr)
{
    int i = blockIdx.x * blockDim.x + threadIdx.x;
    if (i >= PN) return;

    float mx = means[3*i+0], my = means[3*i+1], mz = means[3*i+2];

    float pv0 = mx*Vm[0] + my*Vm[4] + mz*Vm[8]  + Vm[12];
    float pv1 = mx*Vm[1] + my*Vm[5] + mz*Vm[9]  + Vm[13];
    float pv2 = mx*Vm[2] + my*Vm[6] + mz*Vm[10] + Vm[14];

    float ph0 = mx*Pr[0] + my*Pr[4] + mz*Pr[8]  + Pr[12];
    float ph1 = mx*Pr[1] + my*Pr[5] + mz*Pr[9]  + Pr[13];
    float ph3 = mx*Pr[3] + my*Pr[7] + mz*Pr[11] + Pr[15];
    float invw = __fdividef(1.0f, ph3 + 1e-7f);
    float m2x = ((ph0*invw + 1.0f) * (float)WD - 1.0f) * 0.5f;
    float m2y = ((ph1*invw + 1.0f) * (float)HD - 1.0f) * 0.5f;

    float qr = rots[4*i+0], qx = rots[4*i+1], qy = rots[4*i+2], qz = rots[4*i+3];
    float qin = rsqrtf(qr*qr + qx*qx + qy*qy + qz*qz);
    qr *= qin; qx *= qin; qy *= qin; qz *= qin;
    float R[3][3];
    R[0][0] = 1.0f - 2.0f*(qy*qy + qz*qz); R[0][1] = 2.0f*(qx*qy - qr*qz); R[0][2] = 2.0f*(qx*qz + qr*qy);
    R[1][0] = 2.0f*(qx*qy + qr*qz); R[1][1] = 1.0f - 2.0f*(qx*qx + qz*qz); R[1][2] = 2.0f*(qy*qz - qr*qx);
    R[2][0] = 2.0f*(qx*qz - qr*qy); R[2][1] = 2.0f*(qy*qz + qr*qx); R[2][2] = 1.0f - 2.0f*(qx*qx + qy*qy);

    float s0 = scales[3*i+0], s1 = scales[3*i+1], s2 = scales[3*i+2];
    float sq0 = s0*s0, sq1 = s1*s1, sq2 = s2*s2;

    float Sg[3][3];
    #pragma unroll
    for (int r = 0; r < 3; r++)
        #pragma unroll
        for (int c = 0; c < 3; c++)
            Sg[r][c] = R[r][0]*sq0*R[c][0] + R[r][1]*sq1*R[c][1] + R[r][2]*sq2*R[c][2];

    float Mt[3][3], Cc[3][3];
    #pragma unroll
    for (int r = 0; r < 3; r++)
        #pragma unroll
        for (int k = 0; k < 3; k++)
            Mt[r][k] = Vm[0*4+r]*Sg[0][k] + Vm[1*4+r]*Sg[1][k] + Vm[2*4+r]*Sg[2][k];
    #pragma unroll
    for (int r = 0; r < 3; r++)
        #pragma unroll
        for (int l = 0; l < 3; l++)
            Cc[r][l] = Mt[r][0]*Vm[0*4+l] + Mt[r][1]*Vm[1*4+l] + Mt[r][2]*Vm[2*4+l];

    float tz  = pv2;
    float itz = __fdividef(1.0f, tz);
    float limx = 1.3f * TANXc, limy = 1.3f * TANYc;
    float txc = fminf(limx, fmaxf(-limx, pv0*itz)) * tz;
    float tyc = fminf(limy, fmaxf(-limy, pv1*itz)) * tz;
    float J00 = FXc*itz, J02 = -FXc*txc*itz*itz;
    float J11 = FYc*itz, J12 = -FYc*tyc*itz*itz;

    float T00 = J00*Cc[0][0] + J02*Cc[2][0];
    float T01 = J00*Cc[0][1] + J02*Cc[2][1];
    float T02 = J00*Cc[0][2] + J02*Cc[2][2];
    float T11 = J11*Cc[1][1] + J12*Cc[2][1];
    float T12 = J11*Cc[1][2] + J12*Cc[2][2];
    float c00 = T00*J00 + T02*J02;
    float c01 = T01*J11 + T02*J12;
    float c11 = T11*J11 + T12*J12;

    float a = c00 + 0.3f, b = c01, c = c11 + 0.3f;
    float det  = a*c - b*b;
    float idet = __fdividef(1.0f, det);
    float A  = c*idet, B = -b*idet, C2 = a*idet;

    float o   = ops[i];
    float tau = 2.0f * __logf(255.0f * o);
    float tq  = fmaxf(tau, 0.0f);
    float ex  = sqrtf(tq * a) + 1.0f;
    float ey  = sqrtf(tq * c) + 1.0f;

    g_d1[i] = make_float4(m2x, m2y, A, B);
    g_d2[i] = make_float4(C2, o, cols[3*i+0], cols[3*i+1]);
    g_d3[i] = cols[3*i+2];

    if (tau <= 0.0f) return;   // alpha can never reach 1/255

    const float inv = 1.0f / (float)TSZ;
    int rx0 = max(0,       (int)ceilf ((m2x - ex - (float)(TSZ-1)) * inv));
    int rx1 = min(NTX - 1, (int)floorf((m2x + ex) * inv));
    int ry0 = max(0,       (int)ceilf ((m2y - ey - (float)(TSZ-1)) * inv));
    int ry1 = min(NTX - 1, (int)floorf((m2y + ey) * inv));
    if (rx0 > rx1 || ry0 > ry1) return;

    u64 key = ((u64)__float_as_uint(pv2) << 32) | (unsigned)i;
    int sw = rx1 - rx0, sh = ry1 - ry0;

    if (sw <= 3 && sh <= 3) {
        // fully unrolled, predicated: up to 16 INDEPENDENT atomics in flight
        #pragma unroll
        for (int dy = 0; dy < 4; dy++) {
            #pragma unroll
            for (int dx = 0; dx < 4; dx++) {
                if (dy <= sh && dx <= sw) {
                    int t = (ry0 + dy) * NTX + (rx0 + dx);
                    int pos = atomicAdd(&g_tcnt[t], 1);
                    if (pos < TCAP) g_tkey[t * TCAP + pos] = key;
                }
            }
        }
    } else {
        for (int ry = ry0; ry <= ry1; ry++)
            #pragma unroll 4
            for (int rx = rx0; rx <= rx1; rx++) {
                int t = ry * NTX + rx;
                int pos = atomicAdd(&g_tcnt[t], 1);
                if (pos < TCAP) g_tkey[t * TCAP + pos] = key;
            }
    }
}

// ---------------- per-tile depth sort (1024 blocks, 128 thr) + coalesced gather ----------------
__global__ __launch_bounds__(128) void tile_sort_kernel()
{
    __shared__ u64 sk[TCAP];
    const int r = blockIdx.x;
    const int t = threadIdx.x;
    const int n = min(g_tcnt[r], TCAP);
    if (t == 0) {
        g_scnt[r] = n;
        g_tcnt[r] = 0;          // reset for next graph replay
    }
    if (n == 0) return;

    int m = 2;
    while (m < n) m <<= 1;

    for (int i = t; i < m; i += 128)
        sk[i] = (i < n) ? g_tkey[r * TCAP + i] : ~0ull;
    __syncthreads();

    for (int k = 2; k <= m; k <<= 1) {
        for (int j = k >> 1; j > 0; j >>= 1) {
            for (int p = t; p < (m >> 1); p += 128) {
                int i  = ((p & ~(j - 1)) << 1) | (p & (j - 1));
                bool up = ((i & k) == 0);
                u64 x = sk[i], y = sk[i | j];
                if ((x > y) == up) { sk[i] = y; sk[i | j] = x; }
            }
            __syncthreads();
        }
    }

    for (int i = t; i < n; i += 128) {
        int s = (int)(sk[i] & 0xFFFFFFFFu);
        g_ta[r * TCAP + i] = g_d1[s];
        g_tb[r * TCAP + i] = g_d2[s];
        g_tc[r * TCAP + i] = g_d3[s];
    }
}

// ---------------- tiled rasterizer: 8x8 tiles, software-pipelined blend ----------------
__global__ __launch_bounds__(64) void raster_kernel(const float* __restrict__ bg,
                                                    float* __restrict__ out)
{
    const int tx = threadIdx.x, ty = threadIdx.y;
    const int tid = ty * TSZ + tx;
    const int pxi = blockIdx.x * TSZ + tx;
    const int pyi = blockIdx.y * TSZ + ty;
    const float pxf = (float)pxi, pyf = (float)pyi;

    const int r = (int)blockIdx.y * NTX + (int)blockIdx.x;
    const int n = g_scnt[r];
    const int obase = r * TCAP;

    __shared__ float4 s_a[64];   // x, y, A, B
    __shared__ float4 s_b[64];   // C, o, r, g
    __shared__ float  s_c[64];   // b

    float T = 1.0f;
    float ar = 0.0f, ag = 0.0f, ab = 0.0f;
    bool alive = true;

    for (int start = 0; start < n; start += 64) {
        int g = start + tid;
        if (g < n) {
            s_a[tid] = g_ta[obase + g];
            s_b[tid] = g_tb[obase + g];
            s_c[tid] = g_tc[obase + g];
        }
        __syncthreads();
        int cnt = min(64, n - start);

        if (alive) {
            // software-pipelined: prefetch entry jj+1 while blending jj
            float4 na = s_a[0];
            float4 nb = s_b[0];
            float  nc = s_c[0];
            #pragma unroll 2
            for (int jj = 0; jj < cnt; jj++) {
                float4 ea = na;
                float4 eb = nb;
                float  ec = nc;
                int j1 = jj + 1;
                if (j1 < cnt) { na = s_a[j1]; nb = s_b[j1]; nc = s_c[j1]; }

                float dx = ea.x - pxf;
                float dy = ea.y - pyf;
                float power = -0.5f * (ea.z*dx*dx + eb.x*dy*dy) - ea.w*dx*dy;
                float raw = eb.y * __expf(power);     // unconditional; discarded if power>0
                if (power > 0.0f || raw < (1.0f / 255.0f)) continue;
                float alpha = fminf(0.99f, raw);
                float wgt = alpha * T;
                ar += wgt * eb.z;
                ag += wgt * eb.w;
                ab += wgt * ec;
                T *= (1.0f - alpha);
                if (T < 1e-6f) { alive = false; break; }
            }
        }
        int nalive = __syncthreads_count(alive ? 1 : 0);
        if (nalive == 0) break;
    }

    int pid = pyi * WD + pxi;
    out[pid]           = ar + T * bg[0];
    out[HD*WD + pid]   = ag + T * bg[1];
    out[2*HD*WD + pid] = ab + T * bg[2];
}

// ---------------- launch ----------------
extern "C" void kernel_launch(void* const* d_in, const int* in_sizes, int n_in,
                              void* d_out, int out_size)
{
    const float* means  = (const float*)d_in[0];
    const float* cols   = (const float*)d_in[1];
    const float* ops    = (const float*)d_in[2];
    const float* scales = (const float*)d_in[3];
    const float* rots   = (const float*)d_in[4];
    const float* bg     = (const float*)d_in[5];
    const float* Vm     = (const float*)d_in[6];
    const float* Pr     = (const float*)d_in[7];
    float* out = (float*)d_out;

    preprocess_kernel<<<PN/64, 64>>>(means, cols, ops, scales, rots, Vm, Pr);
    tile_sort_kernel<<<NTILE, 128>>>();
    dim3 grid(WD/TSZ, HD/TSZ), block(TSZ, TSZ);
    raster_kernel<<<grid, block>>>(bg, out);
}

// round 9
// speedup vs baseline: 1.0745x; 1.0205x over previous
#include <cuda_runtime.h>

// ---------------- problem constants ----------------
#define PN     8192
#define WD     256
#define HD     256
#define TANXc  0.5f
#define TANYc  0.5f
#define FXc    256.0f
#define FYc    256.0f
#define TSZ    8           // tile size in px
#define NTX    32          // tiles per row
#define NTILE  1024
#define NSUB   8           // counter stripes per tile (atomic contention /8)
#define SUBCAP 512         // capacity per stripe
#define TCAP   1024        // per-tile merged capacity (sort/raster)

typedef unsigned long long u64;

// ---------------- scratch ----------------
__device__ float4 g_d1[PN];                        // x, y, A, B
__device__ float4 g_d2[PN];                        // C, o, r, g
__device__ float  g_d3[PN];                        // b
__device__ u64    g_tkey[NTILE * NSUB * SUBCAP];   // striped per-tile keys
__device__ int    g_tcnt[NTILE * NSUB];            // striped atomic counters
__device__ int    g_scnt[NTILE];                   // merged counts for raster
__device__ float4 g_ta[NTILE * TCAP];              // sorted: x, y, A, B
__device__ float4 g_tb[NTILE * TCAP];              // sorted: C, o, r, g
__device__ float  g_tc[NTILE * TCAP];              // sorted: b

// ---------------- preprocess + striped per-tile binning ----------------
__global__ __launch_bounds__(256) void preprocess_kernel(
    const float* __restrict__ means, const float* __restrict__ cols,
    const float* __restrict__ ops, const float* __restrict__ scales,
    const float* __restrict__ rots, const float* __restrict__ Vm,
    const float* __restrict__ Pr)
{
    int i = blockIdx.x * blockDim.x + threadIdx.x;
    if (i >= PN) return;

    float mx = means[3*i+0], my = means[3*i+1], mz = means[3*i+2];

    float pv0 = mx*Vm[0] + my*Vm[4] + mz*Vm[8]  + Vm[12];
    float pv1 = mx*Vm[1] + my*Vm[5] + mz*Vm[9]  + Vm[13];
    float pv2 = mx*Vm[2] + my*Vm[6] + mz*Vm[10] + Vm[14];

    float ph0 = mx*Pr[0] + my*Pr[4] + mz*Pr[8]  + Pr[12];
    float ph1 = mx*Pr[1] + my*Pr[5] + mz*Pr[9]  + Pr[13];
    float ph3 = mx*Pr[3] + my*Pr[7] + mz*Pr[11] + Pr[15];
    float invw = __fdividef(1.0f, ph3 + 1e-7f);
    float m2x = ((ph0*invw + 1.0f) * (float)WD - 1.0f) * 0.5f;
    float m2y = ((ph1*invw + 1.0f) * (float)HD - 1.0f) * 0.5f;

    float qr = rots[4*i+0], qx = rots[4*i+1], qy = rots[4*i+2], qz = rots[4*i+3];
    float qin = rsqrtf(qr*qr + qx*qx + qy*qy + qz*qz);
    qr *= qin; qx *= qin; qy *= qin; qz *= qin;
    float R[3][3];
    R[0][0] = 1.0f - 2.0f*(qy*qy + qz*qz); R[0][1] = 2.0f*(qx*qy - qr*qz); R[0][2] = 2.0f*(qx*qz + qr*qy);
    R[1][0] = 2.0f*(qx*qy + qr*qz); R[1][1] = 1.0f - 2.0f*(qx*qx + qz*qz); R[1][2] = 2.0f*(qy*qz - qr*qx);
    R[2][0] = 2.0f*(qx*qz - qr*qy); R[2][1] = 2.0f*(qy*qz + qr*qx); R[2][2] = 1.0f - 2.0f*(qx*qx + qy*qy);

    float s0 = scales[3*i+0], s1 = scales[3*i+1], s2 = scales[3*i+2];
    float sq0 = s0*s0, sq1 = s1*s1, sq2 = s2*s2;

    float Sg[3][3];
    #pragma unroll
    for (int r = 0; r < 3; r++)
        #pragma unroll
        for (int c = 0; c < 3; c++)
            Sg[r][c] = R[r][0]*sq0*R[c][0] + R[r][1]*sq1*R[c][1] + R[r][2]*sq2*R[c][2];

    float Mt[3][3], Cc[3][3];
    #pragma unroll
    for (int r = 0; r < 3; r++)
        #pragma unroll
        for (int k = 0; k < 3; k++)
            Mt[r][k] = Vm[0*4+r]*Sg[0][k] + Vm[1*4+r]*Sg[1][k] + Vm[2*4+r]*Sg[2][k];
    #pragma unroll
    for (int r = 0; r < 3; r++)
        #pragma unroll
        for (int l = 0; l < 3; l++)
            Cc[r][l] = Mt[r][0]*Vm[0*4+l] + Mt[r][1]*Vm[1*4+l] + Mt[r][2]*Vm[2*4+l];

    float tz  = pv2;
    float itz = __fdividef(1.0f, tz);
    float limx = 1.3f * TANXc, limy = 1.3f * TANYc;
    float txc = fminf(limx, fmaxf(-limx, pv0*itz)) * tz;
    float tyc = fminf(limy, fmaxf(-limy, pv1*itz)) * tz;
    float J00 = FXc*itz, J02 = -FXc*txc*itz*itz;
    float J11 = FYc*itz, J12 = -FYc*tyc*itz*itz;

    float T00 = J00*Cc[0][0] + J02*Cc[2][0];
    float T01 = J00*Cc[0][1] + J02*Cc[2][1];
    float T02 = J00*Cc[0][2] + J02*Cc[2][2];
    float T11 = J11*Cc[1][1] + J12*Cc[2][1];
    float T12 = J11*Cc[1][2] + J12*Cc[2][2];
    float c00 = T00*J00 + T02*J02;
    float c01 = T01*J11 + T02*J12;
    float c11 = T11*J11 + T12*J12;

    float a = c00 + 0.3f, b = c01, c = c11 + 0.3f;
    float det  = a*c - b*b;
    float idet = __fdividef(1.0f, det);
    float A  = c*idet, B = -b*idet, C2 = a*idet;

    float o   = ops[i];
    float tau = 2.0f * __logf(255.0f * o);
    float tq  = fmaxf(tau, 0.0f);
    float ex  = sqrtf(tq * a) + 1.0f;
    float ey  = sqrtf(tq * c) + 1.0f;

    g_d1[i] = make_float4(m2x, m2y, A, B);
    g_d2[i] = make_float4(C2, o, cols[3*i+0], cols[3*i+1]);
    g_d3[i] = cols[3*i+2];

    if (tau <= 0.0f) return;   // alpha can never reach 1/255

    const float inv = 1.0f / (float)TSZ;
    int rx0 = max(0,       (int)ceilf ((m2x - ex - (float)(TSZ-1)) * inv));
    int rx1 = min(NTX - 1, (int)floorf((m2x + ex) * inv));
    int ry0 = max(0,       (int)ceilf ((m2y - ey - (float)(TSZ-1)) * inv));
    int ry1 = min(NTX - 1, (int)floorf((m2y + ey) * inv));
    if (rx0 > rx1 || ry0 > ry1) return;

    u64 key = ((u64)__float_as_uint(pv2) << 32) | (unsigned)i;
    const int sub = i & (NSUB - 1);       // stripe: contention / 8
    int sw = rx1 - rx0, sh = ry1 - ry0;

    if (sw <= 3 && sh <= 3) {
        #pragma unroll
        for (int dy = 0; dy < 4; dy++) {
            #pragma unroll
            for (int dx = 0; dx < 4; dx++) {
                if (dy <= sh && dx <= sw) {
                    int t = (ry0 + dy) * NTX + (rx0 + dx);
                    int pos = atomicAdd(&g_tcnt[t * NSUB + sub], 1);
                    if (pos < SUBCAP) g_tkey[(t * NSUB + sub) * SUBCAP + pos] = key;
                }
            }
        }
    } else {
        for (int ry = ry0; ry <= ry1; ry++)
            #pragma unroll 4
            for (int rx = rx0; rx <= rx1; rx++) {
                int t = ry * NTX + rx;
                int pos = atomicAdd(&g_tcnt[t * NSUB + sub], 1);
                if (pos < SUBCAP) g_tkey[(t * NSUB + sub) * SUBCAP + pos] = key;
            }
    }
}

// ---------------- per-tile merge of 8 stripes + depth sort + coalesced gather ----------------
__global__ __launch_bounds__(128) void tile_sort_kernel()
{
    __shared__ u64 sk[TCAP];
    __shared__ int soff[NSUB + 1];
    const int r = blockIdx.x;
    const int t = threadIdx.x;

    if (t == 0) {
        int acc = 0;
        #pragma unroll
        for (int s = 0; s < NSUB; s++) {
            soff[s] = acc;
            acc += min(g_tcnt[r * NSUB + s], SUBCAP);
            g_tcnt[r * NSUB + s] = 0;      // reset for next graph replay
        }
        acc = min(acc, TCAP);
        soff[NSUB] = acc;
        g_scnt[r] = acc;
    }
    __syncthreads();
    const int n = soff[NSUB];
    if (n == 0) return;

    // concatenate stripes into smem
    #pragma unroll
    for (int s = 0; s < NSUB; s++) {
        int o0 = soff[s], o1 = min(soff[s + 1], TCAP);
        for (int i = t; i < o1 - o0; i += 128)
            sk[o0 + i] = g_tkey[(r * NSUB + s) * SUBCAP + i];
    }
    int m = 2;
    while (m < n) m <<= 1;
    for (int i = n + t; i < m; i += 128) sk[i] = ~0ull;
    __syncthreads();

    // bitonic sort by depth key
    for (int k = 2; k <= m; k <<= 1) {
        for (int j = k >> 1; j > 0; j >>= 1) {
            for (int p = t; p < (m >> 1); p += 128) {
                int i  = ((p & ~(j - 1)) << 1) | (p & (j - 1));
                bool up = ((i & k) == 0);
                u64 x = sk[i], y = sk[i | j];
                if ((x > y) == up) { sk[i] = y; sk[i | j] = x; }
            }
            __syncthreads();
        }
    }

    // coalesced gather of payload in depth order
    for (int i = t; i < n; i += 128) {
        int s = (int)(sk[i] & 0xFFFFFFFFu);
        g_ta[r * TCAP + i] = g_d1[s];
        g_tb[r * TCAP + i] = g_d2[s];
        g_tc[r * TCAP + i] = g_d3[s];
    }
}

// ---------------- tiled rasterizer: 8x8 tiles, software-pipelined blend ----------------
__global__ __launch_bounds__(64) void raster_kernel(const float* __restrict__ bg,
                                                    float* __restrict__ out)
{
    const int tx = threadIdx.x, ty = threadIdx.y;
    const int tid = ty * TSZ + tx;
    const int pxi = blockIdx.x * TSZ + tx;
    const int pyi = blockIdx.y * TSZ + ty;
    const float pxf = (float)pxi, pyf = (float)pyi;

    const int r = (int)blockIdx.y * NTX + (int)blockIdx.x;
    const int n = g_scnt[r];
    const int obase = r * TCAP;

    __shared__ float4 s_a[64];   // x, y, A, B
    __shared__ float4 s_b[64];   // C, o, r, g
    __shared__ float  s_c[64];   // b

    float T = 1.0f;
    float ar = 0.0f, ag = 0.0f, ab = 0.0f;
    bool alive = true;

    for (int start = 0; start < n; start += 64) {
        int g = start + tid;
        if (g < n) {
            s_a[tid] = g_ta[obase + g];
            s_b[tid] = g_tb[obase + g];
            s_c[tid] = g_tc[obase + g];
        }
        __syncthreads();
        int cnt = min(64, n - start);

        if (alive) {
            // software-pipelined: prefetch entry jj+1 while blending jj
            float4 na = s_a[0];
            float4 nb = s_b[0];
            float  nc = s_c[0];
            #pragma unroll 2
            for (int jj = 0; jj < cnt; jj++) {
                float4 ea = na;
                float4 eb = nb;
                float  ec = nc;
                int j1 = jj + 1;
                if (j1 < cnt) { na = s_a[j1]; nb = s_b[j1]; nc = s_c[j1]; }

                float dx = ea.x - pxf;
                float dy = ea.y - pyf;
                float power = -0.5f * (ea.z*dx*dx + eb.x*dy*dy) - ea.w*dx*dy;
                float raw = eb.y * __expf(power);     // unconditional; discarded if power>0
                if (power > 0.0f || raw < (1.0f / 255.0f)) continue;
                float alpha = fminf(0.99f, raw);
                float wgt = alpha * T;
                ar += wgt * eb.z;
                ag += wgt * eb.w;
                ab += wgt * ec;
                T *= (1.0f - alpha);
                if (T < 1e-6f) { alive = false; break; }
            }
        }
        int nalive = __syncthreads_count(alive ? 1 : 0);
        if (nalive == 0) break;
    }

    int pid = pyi * WD + pxi;
    out[pid]           = ar + T * bg[0];
    out[HD*WD + pid]   = ag + T * bg[1];
    out[2*HD*WD + pid] = ab + T * bg[2];
}

// ---------------- launch ----------------
extern "C" void kernel_launch(void* const* d_in, const int* in_sizes, int n_in,
                              void* d_out, int out_size)
{
    const float* means  = (const float*)d_in[0];
    const float* cols   = (const float*)d_in[1];
    const float* ops    = (const float*)d_in[2];
    const float* scales = (const float*)d_in[3];
    const float* rots   = (const float*)d_in[4];
    const float* bg     = (const float*)d_in[5];
    const float* Vm     = (const float*)d_in[6];
    const float* Pr     = (const float*)d_in[7];
    float* out = (float*)d_out;

    preprocess_kernel<<<PN/256, 256>>>(means, cols, ops, scales, rots, Vm, Pr);
    tile_sort_kernel<<<NTILE, 128>>>();
    dim3 grid(WD/TSZ, HD/TSZ), block(TSZ, TSZ);
    raster_kernel<<<grid, block>>>(bg, out);
}

// round 10
// speedup vs baseline: 1.2780x; 1.1894x over previous
#include <cuda_runtime.h>

// ---------------- problem constants ----------------
#define PN     8192
#define WD     256
#define HD     256
#define TANXc  0.5f
#define TANYc  0.5f
#define FXc    256.0f
#define FYc    256.0f
#define TSZ    8           // tile size in px
#define NTX    32          // tiles per row
#define NTILE  1024
#define TCAP   1024        // per-tile capacity

typedef unsigned long long u64;

// ---------------- scratch ----------------
__device__ float4 g_d1[PN];              // x, y, A, B
__device__ float4 g_d2[PN];              // C, o, r, g
__device__ float  g_d3[PN];              // b
__device__ float4 g_bb[PN];              // mean2d.x, mean2d.y, ext_x, ext_y
__device__ u64    g_key[PN];             // depth_bits<<32 | idx
__device__ int    g_scnt[NTILE];         // per-tile counts
__device__ float4 g_ta[NTILE * TCAP];    // sorted: x, y, A, B
__device__ float4 g_tb[NTILE * TCAP];    // sorted: C, o, r, g
__device__ float  g_tc[NTILE * TCAP];    // sorted: b

// ---------------- preprocess: pure per-gaussian math, NO atomics ----------------
__global__ __launch_bounds__(256) void preprocess_kernel(
    const float* __restrict__ means, const float* __restrict__ cols,
    const float* __restrict__ ops, const float* __restrict__ scales,
    const float* __restrict__ rots, const float* __restrict__ Vm,
    const float* __restrict__ Pr)
{
    int i = blockIdx.x * blockDim.x + threadIdx.x;
    if (i >= PN) return;

    float mx = means[3*i+0], my = means[3*i+1], mz = means[3*i+2];

    float pv0 = mx*Vm[0] + my*Vm[4] + mz*Vm[8]  + Vm[12];
    float pv1 = mx*Vm[1] + my*Vm[5] + mz*Vm[9]  + Vm[13];
    float pv2 = mx*Vm[2] + my*Vm[6] + mz*Vm[10] + Vm[14];

    float ph0 = mx*Pr[0] + my*Pr[4] + mz*Pr[8]  + Pr[12];
    float ph1 = mx*Pr[1] + my*Pr[5] + mz*Pr[9]  + Pr[13];
    float ph3 = mx*Pr[3] + my*Pr[7] + mz*Pr[11] + Pr[15];
    float invw = __fdividef(1.0f, ph3 + 1e-7f);
    float m2x = ((ph0*invw + 1.0f) * (float)WD - 1.0f) * 0.5f;
    float m2y = ((ph1*invw + 1.0f) * (float)HD - 1.0f) * 0.5f;

    float qr = rots[4*i+0], qx = rots[4*i+1], qy = rots[4*i+2], qz = rots[4*i+3];
    float qin = rsqrtf(qr*qr + qx*qx + qy*qy + qz*qz);
    qr *= qin; qx *= qin; qy *= qin; qz *= qin;
    float R[3][3];
    R[0][0] = 1.0f - 2.0f*(qy*qy + qz*qz); R[0][1] = 2.0f*(qx*qy - qr*qz); R[0][2] = 2.0f*(qx*qz + qr*qy);
    R[1][0] = 2.0f*(qx*qy + qr*qz); R[1][1] = 1.0f - 2.0f*(qx*qx + qz*qz); R[1][2] = 2.0f*(qy*qz - qr*qx);
    R[2][0] = 2.0f*(qx*qz - qr*qy); R[2][1] = 2.0f*(qy*qz + qr*qx); R[2][2] = 1.0f - 2.0f*(qx*qx + qy*qy);

    float s0 = scales[3*i+0], s1 = scales[3*i+1], s2 = scales[3*i+2];
    float sq0 = s0*s0, sq1 = s1*s1, sq2 = s2*s2;

    float Sg[3][3];
    #pragma unroll
    for (int r = 0; r < 3; r++)
        #pragma unroll
        for (int c = 0; c < 3; c++)
            Sg[r][c] = R[r][0]*sq0*R[c][0] + R[r][1]*sq1*R[c][1] + R[r][2]*sq2*R[c][2];

    float Mt[3][3], Cc[3][3];
    #pragma unroll
    for (int r = 0; r < 3; r++)
        #pragma unroll
        for (int k = 0; k < 3; k++)
            Mt[r][k] = Vm[0*4+r]*Sg[0][k] + Vm[1*4+r]*Sg[1][k] + Vm[2*4+r]*Sg[2][k];
    #pragma unroll
    for (int r = 0; r < 3; r++)
        #pragma unroll
        for (int l = 0; l < 3; l++)
            Cc[r][l] = Mt[r][0]*Vm[0*4+l] + Mt[r][1]*Vm[1*4+l] + Mt[r][2]*Vm[2*4+l];

    float tz  = pv2;
    float itz = __fdividef(1.0f, tz);
    float limx = 1.3f * TANXc, limy = 1.3f * TANYc;
    float txc = fminf(limx, fmaxf(-limx, pv0*itz)) * tz;
    float tyc = fminf(limy, fmaxf(-limy, pv1*itz)) * tz;
    float J00 = FXc*itz, J02 = -FXc*txc*itz*itz;
    float J11 = FYc*itz, J12 = -FYc*tyc*itz*itz;

    float T00 = J00*Cc[0][0] + J02*Cc[2][0];
    float T01 = J00*Cc[0][1] + J02*Cc[2][1];
    float T02 = J00*Cc[0][2] + J02*Cc[2][2];
    float T11 = J11*Cc[1][1] + J12*Cc[2][1];
    float T12 = J11*Cc[1][2] + J12*Cc[2][2];
    float c00 = T00*J00 + T02*J02;
    float c01 = T01*J11 + T02*J12;
    float c11 = T11*J11 + T12*J12;

    float a = c00 + 0.3f, b = c01, c = c11 + 0.3f;
    float det  = a*c - b*b;
    float idet = __fdividef(1.0f, det);
    float A  = c*idet, B = -b*idet, C2 = a*idet;

    float o   = ops[i];
    float tau = 2.0f * __logf(255.0f * o);
    float tq  = fmaxf(tau, 0.0f);
    float ex  = sqrtf(tq * a) + 1.0f;
    float ey  = sqrtf(tq * c) + 1.0f;
    if (tau <= 0.0f) { ex = -1e30f; ey = -1e30f; }   // never visible

    g_d1[i] = make_float4(m2x, m2y, A, B);
    g_d2[i] = make_float4(C2, o, cols[3*i+0], cols[3*i+1]);
    g_d3[i] = cols[3*i+2];
    g_bb[i] = make_float4(m2x, m2y, ex, ey);
    g_key[i] = ((u64)__float_as_uint(pv2) << 32) | (unsigned)i;   // pv2>0: bit-monotonic
}

// ---------------- per-tile scan + compact + depth sort + gather (no global atomics) ----------------
__global__ __launch_bounds__(128) void tile_sort_kernel()
{
    __shared__ u64 sk[TCAP];
    __shared__ int s_cnt;

    const int r = blockIdx.x;
    const int t = threadIdx.x;
    const float xmin = (float)((r & (NTX - 1)) * TSZ), xmax = xmin + (float)(TSZ - 1);
    const float ymin = (float)((r >> 5) * TSZ),        ymax = ymin + (float)(TSZ - 1);

    if (t == 0) s_cnt = 0;
    __syncthreads();

    // scan all gaussians; AABB-overlap test identical to the old tile-span binning
    for (int base = 0; base < PN; base += 128) {
        float4 bb = g_bb[base + t];
        bool hit = (bb.x + bb.z >= xmin) && (bb.x - bb.z <= xmax) &&
                   (bb.y + bb.w >= ymin) && (bb.y - bb.w <= ymax);
        if (hit) {
            int p = atomicAdd(&s_cnt, 1);      // smem atomic: order-agnostic, sort canonicalizes
            if (p < TCAP) sk[p] = g_key[base + t];
        }
    }
    __syncthreads();

    const int n = min(s_cnt, TCAP);
    g_scnt[r] = n;     // every thread has same value? no — write from t==0 below instead
    if (n == 0) return;

    int m = 2;
    while (m < n) m <<= 1;
    for (int i = n + t; i < m; i += 128) sk[i] = ~0ull;
    __syncthreads();

    // bitonic sort by depth key
    for (int k = 2; k <= m; k <<= 1) {
        for (int j = k >> 1; j > 0; j >>= 1) {
            for (int p = t; p < (m >> 1); p += 128) {
                int i  = ((p & ~(j - 1)) << 1) | (p & (j - 1));
                bool up = ((i & k) == 0);
                u64 x = sk[i], y = sk[i | j];
                if ((x > y) == up) { sk[i] = y; sk[i | j] = x; }
            }
            __syncthreads();
        }
    }

    // coalesced-write gather of payload in depth order
    for (int i = t; i < n; i += 128) {
        int s = (int)(sk[i] & 0xFFFFFFFFu);
        g_ta[r * TCAP + i] = g_d1[s];
        g_tb[r * TCAP + i] = g_d2[s];
        g_tc[r * TCAP + i] = g_d3[s];
    }
}

// ---------------- tiled rasterizer: 8x8 tiles, software-pipelined blend ----------------
__global__ __launch_bounds__(64) void raster_kernel(const float* __restrict__ bg,
                                                    float* __restrict__ out)
{
    const int tx = threadIdx.x, ty = threadIdx.y;
    const int tid = ty * TSZ + tx;
    const int pxi = blockIdx.x * TSZ + tx;
    const int pyi = blockIdx.y * TSZ + ty;
    const float pxf = (float)pxi, pyf = (float)pyi;

    const int r = (int)blockIdx.y * NTX + (int)blockIdx.x;
    const int n = g_scnt[r];
    const int obase = r * TCAP;

    __shared__ float4 s_a[64];   // x, y, A, B
    __shared__ float4 s_b[64];   // C, o, r, g
    __shared__ float  s_c[64];   // b

    float T = 1.0f;
    float ar = 0.0f, ag = 0.0f, ab = 0.0f;
    bool alive = true;

    for (int start = 0; start < n; start += 64) {
        int g = start + tid;
        if (g < n) {
            s_a[tid] = g_ta[obase + g];
            s_b[tid] = g_tb[obase + g];
            s_c[tid] = g_tc[obase + g];
        }
        __syncthreads();
        int cnt = min(64, n - start);

        if (alive) {
            // software-pipelined: prefetch entry jj+1 while blending jj
            float4 na = s_a[0];
            float4 nb = s_b[0];
            float  nc = s_c[0];
            #pragma unroll 2
            for (int jj = 0; jj < cnt; jj++) {
                float4 ea = na;
                float4 eb = nb;
                float  ec = nc;
                int j1 = jj + 1;
                if (j1 < cnt) { na = s_a[j1]; nb = s_b[j1]; nc = s_c[j1]; }

                float dx = ea.x - pxf;
                float dy = ea.y - pyf;
                float power = -0.5f * (ea.z*dx*dx + eb.x*dy*dy) - ea.w*dx*dy;
                float raw = eb.y * __expf(power);     // unconditional; discarded if power>0
                if (power > 0.0f || raw < (1.0f / 255.0f)) continue;
                float alpha = fminf(0.99f, raw);
                float wgt = alpha * T;
                ar += wgt * eb.z;
                ag += wgt * eb.w;
                ab += wgt * ec;
                T *= (1.0f - alpha);
                if (T < 1e-6f) { alive = false; break; }
            }
        }
        int nalive = __syncthreads_count(alive ? 1 : 0);
        if (nalive == 0) break;
    }

    int pid = pyi * WD + pxi;
    out[pid]           = ar + T * bg[0];
    out[HD*WD + pid]   = ag + T * bg[1];
    out[2*HD*WD + pid] = ab + T * bg[2];
}

// ---------------- launch ----------------
extern "C" void kernel_launch(void* const* d_in, const int* in_sizes, int n_in,
                              void* d_out, int out_size)
{
    const float* means  = (const float*)d_in[0];
    const float* cols   = (const float*)d_in[1];
    const float* ops    = (const float*)d_in[2];
    const float* scales = (const float*)d_in[3];
    const float* rots   = (const float*)d_in[4];
    const float* bg     = (const float*)d_in[5];
    const float* Vm     = (const float*)d_in[6];
    const float* Pr     = (const float*)d_in[7];
    float* out = (float*)d_out;

    preprocess_kernel<<<PN/256, 256>>>(means, cols, ops, scales, rots, Vm, Pr);
    tile_sort_kernel<<<NTILE, 128>>>();
    dim3 grid(WD/TSZ, HD/TSZ), block(TSZ, TSZ);
    raster_kernel<<<grid, block>>>(bg, out);
}